// round 7
// baseline (speedup 1.0000x reference)
#include <cuda_runtime.h>
#include <cstdint>

#define N 8192
#define THREADS 256
#define GRID 304                               // 2 CTAs/SM x 152 SMs
#define RPC 4                                  // rows per chunk
#define CCOLS 2048                             // cols per chunk
#define COLCH (N / CCOLS)                      // 4
#define TOTAL_CHUNKS ((N / RPC) * COLCH)       // 8192
#define STAGES 3
#define STAGE_FLOATS (RPC * CCOLS)             // 8192 floats = 32 KB
#define STAGE_BYTES (STAGE_FLOATS * 4)
#define ROW_BYTES (CCOLS * 4)                  // 8 KB per row copy
#define INVALID_ID 0xFFFFFFFFu

typedef unsigned long long ull;
union f2u { float2 f; ull u; };

__device__ float        g_xs[N];
__device__ float        g_ys[N];
__device__ float        g_partials[TOTAL_CHUNKS];
__device__ unsigned int g_chunk = 0;
__device__ unsigned int g_count = 0;

__device__ __forceinline__ ull f2add(ull a, ull b) {
    ull c; asm("add.rn.f32x2 %0, %1, %2;" : "=l"(c) : "l"(a), "l"(b)); return c;
}
__device__ __forceinline__ ull f2mul(ull a, ull b) {
    ull c; asm("mul.rn.f32x2 %0, %1, %2;" : "=l"(c) : "l"(a), "l"(b)); return c;
}
__device__ __forceinline__ ull f2fma(ull a, ull b, ull c) {
    ull d; asm("fma.rn.f32x2 %0, %1, %2, %3;" : "=l"(d) : "l"(a), "l"(b), "l"(c)); return d;
}
__device__ __forceinline__ float fsqrt_a(float x) {
    float r; asm("sqrt.approx.f32 %0, %1;" : "=f"(r) : "f"(x)); return r;
}
__device__ __forceinline__ float frcp_a(float x) {
    float r; asm("rcp.approx.f32 %0, %1;" : "=f"(r) : "f"(x)); return r;
}
__device__ __forceinline__ uint32_t smem_u32(const void* p) {
    return (uint32_t)__cvta_generic_to_shared(p);
}
__device__ __forceinline__ void mbar_init(uint32_t mb, uint32_t cnt) {
    asm volatile("mbarrier.init.shared.b64 [%0], %1;" :: "r"(mb), "r"(cnt) : "memory");
}
__device__ __forceinline__ void mbar_expect_tx(uint32_t mb, uint32_t bytes) {
    asm volatile("mbarrier.arrive.expect_tx.shared.b64 _, [%0], %1;"
                 :: "r"(mb), "r"(bytes) : "memory");
}
__device__ __forceinline__ void mbar_wait(uint32_t mb, uint32_t parity) {
    uint32_t done;
    asm volatile(
        "{\n\t.reg .pred p;\n\t"
        "mbarrier.try_wait.parity.acquire.cta.shared::cta.b64 p, [%1], %2;\n\t"
        "selp.b32 %0, 1, 0, p;\n\t}"
        : "=r"(done) : "r"(mb), "r"(parity) : "memory");
    if (!done) {
        asm volatile(
            "{\n\t.reg .pred P1;\n\t"
            "WAIT_LOOP_%=:\n\t"
            "mbarrier.try_wait.parity.acquire.cta.shared::cta.b64 P1, [%0], %1, 0x989680;\n\t"
            "@P1 bra.uni WAIT_DONE_%=;\n\t"
            "bra.uni WAIT_LOOP_%=;\n\t"
            "WAIT_DONE_%=:\n\t}"
            :: "r"(mb), "r"(parity) : "memory");
    }
}
__device__ __forceinline__ void bulk_g2s(uint32_t dst, const void* src,
                                         uint32_t bytes, uint32_t mb) {
    asm volatile(
        "cp.async.bulk.shared::cluster.global.mbarrier::complete_tx::bytes "
        "[%0], [%1], %2, [%3];"
        :: "r"(dst), "l"(src), "r"(bytes), "r"(mb) : "memory");
}

__global__ void soa_kernel(const float2* __restrict__ pos2) {
    int i = blockIdx.x * blockDim.x + threadIdx.x;
    float2 p = pos2[i];
    g_xs[i] = p.x;
    g_ys[i] = p.y;
}

extern __shared__ float s_buf[];               // STAGES * STAGE_FLOATS

__global__ __launch_bounds__(THREADS)
void stress_kernel(const float2* __restrict__ pos2,
                   const float*  __restrict__ dist,
                   float* __restrict__ out) {
    __shared__ uint64_t s_mbar[STAGES];
    __shared__ unsigned s_ids[STAGES];
    __shared__ float    warpsum[THREADS / 32];
    __shared__ bool     is_last;

    const int tid  = threadIdx.x;
    const int lane = tid & 31;
    const int wid  = tid >> 5;

    f2u NEG1; NEG1.f.x = -1.f; NEG1.f.y = -1.f;

    // claim a chunk and issue its TMA into `slot` (thread 0 only)
    auto claim_issue = [&](int slot) {
        unsigned id = atomicAdd(&g_chunk, 1u);
        if (id >= TOTAL_CHUNKS) { s_ids[slot] = INVALID_ID; return; }
        s_ids[slot] = id;
        uint32_t mb = smem_u32(&s_mbar[slot]);
        mbar_expect_tx(mb, STAGE_BYTES);
        const float* src = dist + (size_t)(id / COLCH) * RPC * N
                                + (size_t)(id % COLCH) * CCOLS;
        uint32_t dst = smem_u32(s_buf + slot * STAGE_FLOATS);
        #pragma unroll
        for (int r = 0; r < RPC; r++)
            bulk_g2s(dst + r * ROW_BYTES, src + (size_t)r * N, ROW_BYTES, mb);
    };

    if (tid == 0) {
        #pragma unroll
        for (int s = 0; s < STAGES; s++) mbar_init(smem_u32(&s_mbar[s]), 1);
    }
    __syncthreads();

    // prologue: fill STAGES-1 slots
    if (tid == 0) {
        for (int k = 0; k < STAGES - 1; k++) claim_issue(k);
    }
    __syncthreads();

    for (unsigned t = 0;; t++) {
        const int slot = (int)(t % STAGES);
        const unsigned id = s_ids[slot];
        if (id == INVALID_ID) break;

        mbar_wait(smem_u32(&s_mbar[slot]), (t / STAGES) & 1u);

        // ---- compute chunk ----
        const int row0 = (int)(id / COLCH) * RPC;
        const int col0 = (int)(id % COLCH) * CCOLS;
        const float* buf = s_buf + slot * STAGE_FLOATS;

        f2u nx[RPC], ny[RPC];
        #pragma unroll
        for (int k = 0; k < RPC; k++) {
            float2 p = __ldg(&pos2[row0 + k]);
            nx[k].f.x = -p.x; nx[k].f.y = -p.x;
            ny[k].f.x = -p.y; ny[k].f.y = -p.y;
        }

        f2u acc01, acc23;
        acc01.f.x = 0.f; acc01.f.y = 0.f;
        acc23.f.x = 0.f; acc23.f.y = 0.f;
        float acc_s = 0.f;

        #pragma unroll
        for (int h = 0; h < 2; h++) {
            const int c = tid * 8 + h * 4;            // column offset in chunk

            float4 d0 = *reinterpret_cast<const float4*>(buf + 0 * CCOLS + c);
            float4 d1 = *reinterpret_cast<const float4*>(buf + 1 * CCOLS + c);
            float4 d2 = *reinterpret_cast<const float4*>(buf + 2 * CCOLS + c);
            float4 d3 = *reinterpret_cast<const float4*>(buf + 3 * CCOLS + c);

            float4 x4 = __ldg(reinterpret_cast<const float4*>(&g_xs[col0 + c]));
            float4 y4 = __ldg(reinterpret_cast<const float4*>(&g_ys[col0 + c]));

            float m0 = fminf(fminf(d0.x, d0.y), fminf(d0.z, d0.w));
            float m1 = fminf(fminf(d1.x, d1.y), fminf(d1.z, d1.w));
            float m2 = fminf(fminf(d2.x, d2.y), fminf(d2.z, d2.w));
            float m3 = fminf(fminf(d3.x, d3.y), fminf(d3.z, d3.w));
            float mn = fminf(fminf(m0, m1), fminf(m2, m3));

            if (mn > 0.0f) {
                f2u xa, xb, ya, yb;
                xa.f.x = x4.x; xa.f.y = x4.y;  xb.f.x = x4.z; xb.f.y = x4.w;
                ya.f.x = y4.x; ya.f.y = y4.y;  yb.f.x = y4.z; yb.f.y = y4.w;

                auto grp = [&](const float4& d, ull nxp, ull nyp) {
                    // Montgomery batched reciprocal: 1 MUFU.RCP / 4 elems
                    float p01   = d.x * d.y;
                    float p012  = p01 * d.z;
                    float p0123 = p012 * d.w;
                    float R  = frcp_a(p0123);
                    float i3 = p012 * R;  float R3 = R  * d.w;
                    float i2 = p01  * R3; float R2 = R3 * d.z;
                    float i1 = d.x  * R2; float i0 = d.y * R2;
                    f2u iv01; iv01.f.x = i0; iv01.f.y = i1;
                    f2u iv23; iv23.f.x = i2; iv23.f.y = i3;

                    ull dxa = f2add(xa.u, nxp);
                    ull dya = f2add(ya.u, nyp);
                    ull sqa = f2fma(dya, dya, f2mul(dxa, dxa));
                    f2u sa; sa.u = sqa;
                    f2u pa; pa.f.x = fsqrt_a(sa.f.x); pa.f.y = fsqrt_a(sa.f.y);
                    ull uaa = f2fma(pa.u, iv01.u, NEG1.u);   // pred/d - 1
                    acc01.u = f2fma(uaa, uaa, acc01.u);

                    ull dxb = f2add(xb.u, nxp);
                    ull dyb = f2add(yb.u, nyp);
                    ull sqb = f2fma(dyb, dyb, f2mul(dxb, dxb));
                    f2u sb; sb.u = sqb;
                    f2u pb; pb.f.x = fsqrt_a(sb.f.x); pb.f.y = fsqrt_a(sb.f.y);
                    ull ubb = f2fma(pb.u, iv23.u, NEG1.u);
                    acc23.u = f2fma(ubb, ubb, acc23.u);
                };

                grp(d0, nx[0].u, ny[0].u);
                grp(d1, nx[1].u, ny[1].u);
                grp(d2, nx[2].u, ny[2].u);
                grp(d3, nx[3].u, ny[3].u);
            } else {
                auto safe = [&](float d, float xj, float yj, float px, float py) {
                    float dx = xj + px, dy = yj + py;
                    float sq = fmaf(dy, dy, dx * dx);
                    float pr = fsqrt_a(sq);
                    float q  = (pr - d) * frcp_a(d);
                    q = (d != 0.0f) ? q : 0.0f;
                    acc_s = fmaf(q, q, acc_s);
                };
                const float4 dd[4] = {d0, d1, d2, d3};
                #pragma unroll
                for (int k = 0; k < RPC; k++) {
                    safe(dd[k].x, x4.x, y4.x, nx[k].f.x, ny[k].f.x);
                    safe(dd[k].y, x4.y, y4.y, nx[k].f.x, ny[k].f.x);
                    safe(dd[k].z, x4.z, y4.z, nx[k].f.x, ny[k].f.x);
                    safe(dd[k].w, x4.w, y4.w, nx[k].f.x, ny[k].f.x);
                }
            }
        }

        // per-chunk deterministic reduction (depends only on chunk id)
        float acc = (acc01.f.x + acc01.f.y) + (acc23.f.x + acc23.f.y) + acc_s;
        #pragma unroll
        for (int o = 16; o > 0; o >>= 1)
            acc += __shfl_down_sync(0xffffffffu, acc, o);
        if (lane == 0) warpsum[wid] = acc;
        __syncthreads();                    // buffer free + warpsums ready

        if (tid == 0) {
            float v = 0.0f;
            #pragma unroll
            for (int w = 0; w < THREADS / 32; w++) v += warpsum[w];
            g_partials[id] = v;
            claim_issue((slot + STAGES - 1) % STAGES);   // refill freed slot
        }
        __syncthreads();                    // publish s_ids / protect warpsum
    }

    if (tid == 0) {
        __threadfence();
        unsigned prev = atomicAdd(&g_count, 1u);
        is_last = (prev == GRID - 1);
    }
    __syncthreads();

    if (is_last) {
        // fixed-order final reduction over chunk-indexed partials
        __shared__ double s[THREADS];
        double tsum = 0.0;
        const float4* p4 = reinterpret_cast<const float4*>(g_partials);
        #pragma unroll
        for (int k = 0; k < TOTAL_CHUNKS / THREADS / 4; k++) {
            float4 v = p4[tid * (TOTAL_CHUNKS / THREADS / 4) + k];
            tsum += (double)v.x + (double)v.y + (double)v.z + (double)v.w;
        }
        s[tid] = tsum;
        __syncthreads();
        #pragma unroll
        for (int o = THREADS / 2; o > 0; o >>= 1) {
            if (tid < o) s[tid] += s[tid + o];
            __syncthreads();
        }
        if (tid == 0) {
            out[0] = (float)s[0];
            g_chunk = 0;                   // reset for next graph replay
            g_count = 0;
        }
    }
}

extern "C" void kernel_launch(void* const* d_in, const int* in_sizes, int n_in,
                              void* d_out, int out_size) {
    const float* a = (const float*)d_in[0];
    const float* b = (const float*)d_in[1];
    const float2* pos2;
    const float*  dist;
    if (in_sizes[0] < in_sizes[1]) { pos2 = (const float2*)a; dist = b; }
    else                           { pos2 = (const float2*)b; dist = a; }

    cudaFuncSetAttribute(stress_kernel,
                         cudaFuncAttributeMaxDynamicSharedMemorySize,
                         STAGES * STAGE_BYTES);

    soa_kernel<<<N / 256, 256>>>(pos2);
    stress_kernel<<<GRID, THREADS, STAGES * STAGE_BYTES>>>(pos2, dist, (float*)d_out);
}

// round 8
// speedup vs baseline: 1.3297x; 1.3297x over previous
#include <cuda_runtime.h>
#include <cstdint>

#define N 8192
#define THREADS 256
#define GRID 456                         // 3 CTAs/SM x 152 SMs
#define RPU 4                            // rows per unit
#define CCOLS 4096                       // cols per unit (half row)
#define COLCH 2
#define UNITS ((N / RPU) * COLCH)        // 4096
#define ITERS (CCOLS / (THREADS * 4))    // 4
#define INVALID_ID 0xFFFFFFFFu

typedef unsigned long long ull;
union f2u { float2 f; ull u; };

__device__ float        g_xs[N];
__device__ float        g_ys[N];
__device__ float        g_partials[UNITS];
__device__ unsigned int g_unit  = 0;
__device__ unsigned int g_count = 0;

__device__ __forceinline__ ull f2add(ull a, ull b) {
    ull c; asm("add.rn.f32x2 %0, %1, %2;" : "=l"(c) : "l"(a), "l"(b)); return c;
}
__device__ __forceinline__ ull f2mul(ull a, ull b) {
    ull c; asm("mul.rn.f32x2 %0, %1, %2;" : "=l"(c) : "l"(a), "l"(b)); return c;
}
__device__ __forceinline__ ull f2fma(ull a, ull b, ull c) {
    ull d; asm("fma.rn.f32x2 %0, %1, %2, %3;" : "=l"(d) : "l"(a), "l"(b), "l"(c)); return d;
}
__device__ __forceinline__ float fsqrt_a(float x) {
    float r; asm("sqrt.approx.f32 %0, %1;" : "=f"(r) : "f"(x)); return r;
}
__device__ __forceinline__ float frcp_a(float x) {
    float r; asm("rcp.approx.f32 %0, %1;" : "=f"(r) : "f"(x)); return r;
}

__global__ void soa_kernel(const float2* __restrict__ pos2) {
    int i = blockIdx.x * blockDim.x + threadIdx.x;
    float2 p = pos2[i];
    g_xs[i] = p.x;
    g_ys[i] = p.y;
}

__global__ __launch_bounds__(THREADS, 3)
void stress_kernel(const float2* __restrict__ pos2,
                   const float*  __restrict__ dist,
                   float* __restrict__ out) {
    __shared__ unsigned s_next;
    __shared__ float    warpsum[THREADS / 32];
    __shared__ bool     is_last;

    const int tid  = threadIdx.x;
    const int lane = tid & 31;
    const int wid  = tid >> 5;

    f2u NEG1; NEG1.f.x = -1.f; NEG1.f.y = -1.f;

    // ---- claim first unit + prefetch its iter0 ----
    if (tid == 0) s_next = atomicAdd(&g_unit, 1u);
    __syncthreads();
    unsigned u = s_next;

    f2u nx[RPU], ny[RPU];
    float4 d0, d1, d2, d3;
    const float* ubase = dist;                 // unit base pointer (row0, col0)

    if (u < UNITS) {
        const int row0 = (int)(u >> 1) * RPU;
        const int col0 = (int)(u & 1) * CCOLS;
        ubase = dist + (size_t)row0 * N + col0;
        #pragma unroll
        for (int k = 0; k < RPU; k++) {
            float2 p = __ldg(&pos2[row0 + k]);
            nx[k].f.x = -p.x; nx[k].f.y = -p.x;
            ny[k].f.x = -p.y; ny[k].f.y = -p.y;
        }
        const int c = tid * 4;
        d0 = __ldcs(reinterpret_cast<const float4*>(ubase + 0 * N + c));
        d1 = __ldcs(reinterpret_cast<const float4*>(ubase + 1 * N + c));
        d2 = __ldcs(reinterpret_cast<const float4*>(ubase + 2 * N + c));
        d3 = __ldcs(reinterpret_cast<const float4*>(ubase + 3 * N + c));
    }

    while (u < UNITS) {
        const int col0 = (int)(u & 1) * CCOLS;

        // claim the NEXT unit early; atomic latency overlaps unit compute
        if (tid == 0) s_next = atomicAdd(&g_unit, 1u);

        f2u acc01, acc23;
        acc01.f.x = 0.f; acc01.f.y = 0.f;
        acc23.f.x = 0.f; acc23.f.y = 0.f;
        float acc_s = 0.f;

        // next-unit state (filled before last iteration)
        unsigned nu = INVALID_ID;
        const float* nbase = dist;
        f2u nnx[RPU], nny[RPU];
        float4 e0, e1, e2, e3;

        #pragma unroll
        for (int it = 0; it < ITERS; it++) {
            const int c = (it * THREADS + tid) * 4;

            // stage the following tile
            float4 f0, f1, f2, f3;
            if (it + 1 < ITERS) {
                const int cn = ((it + 1) * THREADS + tid) * 4;
                f0 = __ldcs(reinterpret_cast<const float4*>(ubase + 0 * N + cn));
                f1 = __ldcs(reinterpret_cast<const float4*>(ubase + 1 * N + cn));
                f2 = __ldcs(reinterpret_cast<const float4*>(ubase + 2 * N + cn));
                f3 = __ldcs(reinterpret_cast<const float4*>(ubase + 3 * N + cn));
            }
            if (it == ITERS - 2) {
                // publish s_next, then prefetch next unit's iter0 during the
                // tail of this unit (overlaps DRAM latency with compute+reduce)
                __syncthreads();
                nu = s_next;
                if (nu < UNITS) {
                    const int nrow0 = (int)(nu >> 1) * RPU;
                    const int ncol0 = (int)(nu & 1) * CCOLS;
                    nbase = dist + (size_t)nrow0 * N + ncol0;
                    #pragma unroll
                    for (int k = 0; k < RPU; k++) {
                        float2 p = __ldg(&pos2[nrow0 + k]);
                        nnx[k].f.x = -p.x; nnx[k].f.y = -p.x;
                        nny[k].f.x = -p.y; nny[k].f.y = -p.y;
                    }
                    const int cc = tid * 4;
                    e0 = __ldcs(reinterpret_cast<const float4*>(nbase + 0 * N + cc));
                    e1 = __ldcs(reinterpret_cast<const float4*>(nbase + 1 * N + cc));
                    e2 = __ldcs(reinterpret_cast<const float4*>(nbase + 2 * N + cc));
                    e3 = __ldcs(reinterpret_cast<const float4*>(nbase + 3 * N + cc));
                }
            }

            float4 x4 = __ldg(reinterpret_cast<const float4*>(&g_xs[col0 + c]));
            float4 y4 = __ldg(reinterpret_cast<const float4*>(&g_ys[col0 + c]));

            float m0 = fminf(fminf(d0.x, d0.y), fminf(d0.z, d0.w));
            float m1 = fminf(fminf(d1.x, d1.y), fminf(d1.z, d1.w));
            float m2 = fminf(fminf(d2.x, d2.y), fminf(d2.z, d2.w));
            float m3 = fminf(fminf(d3.x, d3.y), fminf(d3.z, d3.w));
            float mn = fminf(fminf(m0, m1), fminf(m2, m3));

            if (mn > 0.0f) {
                f2u xa, xb, ya, yb;
                xa.f.x = x4.x; xa.f.y = x4.y;  xb.f.x = x4.z; xb.f.y = x4.w;
                ya.f.x = y4.x; ya.f.y = y4.y;  yb.f.x = y4.z; yb.f.y = y4.w;

                auto grp = [&](const float4& d, ull nxp, ull nyp) {
                    // Montgomery batched reciprocal: 1 MUFU.RCP / 4 elems
                    float p01   = d.x * d.y;
                    float p012  = p01 * d.z;
                    float p0123 = p012 * d.w;
                    float R  = frcp_a(p0123);
                    float i3 = p012 * R;  float R3 = R  * d.w;
                    float i2 = p01  * R3; float R2 = R3 * d.z;
                    float i1 = d.x  * R2; float i0 = d.y * R2;
                    f2u iv01; iv01.f.x = i0; iv01.f.y = i1;
                    f2u iv23; iv23.f.x = i2; iv23.f.y = i3;

                    ull dxa = f2add(xa.u, nxp);
                    ull dya = f2add(ya.u, nyp);
                    ull sqa = f2fma(dya, dya, f2mul(dxa, dxa));
                    f2u sa; sa.u = sqa;
                    f2u pa; pa.f.x = fsqrt_a(sa.f.x); pa.f.y = fsqrt_a(sa.f.y);
                    ull uaa = f2fma(pa.u, iv01.u, NEG1.u);   // pred/d - 1
                    acc01.u = f2fma(uaa, uaa, acc01.u);

                    ull dxb = f2add(xb.u, nxp);
                    ull dyb = f2add(yb.u, nyp);
                    ull sqb = f2fma(dyb, dyb, f2mul(dxb, dxb));
                    f2u sb; sb.u = sqb;
                    f2u pb; pb.f.x = fsqrt_a(sb.f.x); pb.f.y = fsqrt_a(sb.f.y);
                    ull ubb = f2fma(pb.u, iv23.u, NEG1.u);
                    acc23.u = f2fma(ubb, ubb, acc23.u);
                };

                grp(d0, nx[0].u, ny[0].u);
                grp(d1, nx[1].u, ny[1].u);
                grp(d2, nx[2].u, ny[2].u);
                grp(d3, nx[3].u, ny[3].u);
            } else {
                auto safe = [&](float d, float xj, float yj, float px, float py) {
                    float dx = xj + px, dy = yj + py;
                    float sq = fmaf(dy, dy, dx * dx);
                    float pr = fsqrt_a(sq);
                    float q  = (pr - d) * frcp_a(d);
                    q = (d != 0.0f) ? q : 0.0f;
                    acc_s = fmaf(q, q, acc_s);
                };
                const float4 dd[4] = {d0, d1, d2, d3};
                #pragma unroll
                for (int k = 0; k < RPU; k++) {
                    safe(dd[k].x, x4.x, y4.x, nx[k].f.x, ny[k].f.x);
                    safe(dd[k].y, x4.y, y4.y, nx[k].f.x, ny[k].f.x);
                    safe(dd[k].z, x4.z, y4.z, nx[k].f.x, ny[k].f.x);
                    safe(dd[k].w, x4.w, y4.w, nx[k].f.x, ny[k].f.x);
                }
            }

            if (it + 1 < ITERS) { d0 = f0; d1 = f1; d2 = f2; d3 = f3; }
        }

        // per-unit deterministic reduction (value depends only on unit id)
        float acc = (acc01.f.x + acc01.f.y) + (acc23.f.x + acc23.f.y) + acc_s;
        #pragma unroll
        for (int o = 16; o > 0; o >>= 1)
            acc += __shfl_down_sync(0xffffffffu, acc, o);
        if (lane == 0) warpsum[wid] = acc;
        __syncthreads();
        if (tid == 0) {
            float v = 0.0f;
            #pragma unroll
            for (int w = 0; w < THREADS / 32; w++) v += warpsum[w];
            g_partials[u] = v;
        }
        // no extra sync needed: warpsum rewritten only after next unit's
        // mid-loop __syncthreads; s_next re-claimed after that same barrier

        // rotate to next unit (iter0 already in flight)
        u = nu;
        ubase = nbase;
        #pragma unroll
        for (int k = 0; k < RPU; k++) { nx[k] = nnx[k]; ny[k] = nny[k]; }
        d0 = e0; d1 = e1; d2 = e2; d3 = e3;
    }

    if (tid == 0) {
        __threadfence();
        unsigned prev = atomicAdd(&g_count, 1u);
        is_last = (prev == GRID - 1);
    }
    __syncthreads();

    if (is_last) {
        __shared__ double s[THREADS];
        double tsum = 0.0;
        const float4* p4 = reinterpret_cast<const float4*>(g_partials);
        #pragma unroll
        for (int k = 0; k < UNITS / THREADS / 4; k++) {
            float4 v = p4[tid * (UNITS / THREADS / 4) + k];
            tsum += (double)v.x + (double)v.y + (double)v.z + (double)v.w;
        }
        s[tid] = tsum;
        __syncthreads();
        #pragma unroll
        for (int o = THREADS / 2; o > 0; o >>= 1) {
            if (tid < o) s[tid] += s[tid + o];
            __syncthreads();
        }
        if (tid == 0) {
            out[0] = (float)s[0];
            g_unit  = 0;                  // reset for next graph replay
            g_count = 0;
        }
    }
}

extern "C" void kernel_launch(void* const* d_in, const int* in_sizes, int n_in,
                              void* d_out, int out_size) {
    const float* a = (const float*)d_in[0];
    const float* b = (const float*)d_in[1];
    const float2* pos2;
    const float*  dist;
    if (in_sizes[0] < in_sizes[1]) { pos2 = (const float2*)a; dist = b; }
    else                           { pos2 = (const float2*)b; dist = a; }

    soa_kernel<<<N / 256, 256>>>(pos2);
    stress_kernel<<<GRID, THREADS>>>(pos2, dist, (float*)d_out);
}